// round 13
// baseline (speedup 1.0000x reference)
#include <cuda_runtime.h>
#include <cstdint>

// Problem constants (fixed by the reference).
#define ROWS       8192
#define COLS       8192
#define NUMEL      (1ULL * ROWS * COLS)          // 64M output floats
#define NCODES     (NUMEL / 4)                   // 16M codes (centroid_len = 4)
#define CB_ENTRIES 512                           // 2 codebooks * 256 centroids (float4)

#define BLOCK      256
#define WARPS      (BLOCK / 32)                   // 8
#define CPT        8                              // codes per thread per warp-tile
#define WT_CODES   (32 * CPT)                     // 256 codes per warp-tile
#define WT_BYTES   (WT_CODES * 16)                // 4 KB output per warp-tile
#define NWT        ((int)(NCODES / WT_CODES))     // 65536 (exact)
#define HALF_WT    (NWT / 2)                      // codebook boundary in warp-tiles
#define GRID       (152 * 3)                      // 456 blocks (72KB smem -> 3/SM)

// Warp-autonomous dequant: NO block barriers in the main loop. Each warp owns
// a private double-buffered 4KB smem slab and its own cp.async.bulk store
// chain. 24 independent warp-pipelines per SM cover LDG latency and store
// waits with each other's compute; DRAM sees contiguous 4KB write bursts.

__device__ __forceinline__ uint32_t smem_u32(const void* p) {
    uint32_t a;
    asm("{ .reg .u64 t; cvta.to.shared.u64 t, %1; cvt.u32.u64 %0, t; }"
        : "=r"(a) : "l"(p));
    return a;
}

__global__ __launch_bounds__(BLOCK) void dequant_kernel(
    const float4* __restrict__ codebooks,   // [512] float4
    const float*  __restrict__ scales,      // [NUMEL/64]
    const int*    __restrict__ codes,       // [NCODES]
    float4*       __restrict__ out4)        // [NCODES]
{
    __shared__ float4 s_cb[CB_ENTRIES];                          // 8 KB
    __shared__ __align__(128) float4 s_out[WARPS][2][WT_CODES];  // 8 x 8 KB

    for (int i = threadIdx.x; i < CB_ENTRIES; i += BLOCK)
        s_cb[i] = codebooks[i];
    __syncthreads();   // only block barrier in the kernel

    const int wid  = threadIdx.x >> 5;
    const int lane = threadIdx.x & 31;
    const int warp_stride = gridDim.x * WARPS;

    int iter = 0;
    for (int wt = blockIdx.x * WARPS + wid; wt < NWT;
         wt += warp_stride, iter++) {

        const int buf = iter & 1;
        const long long base = (long long)wt * WT_CODES;
        const int cb_off = (wt >= HALF_WT) ? 256 : 0;

        const int*   cp = codes  + base;
        const float* sp = scales + (base >> 4);   // 16 scales per warp-tile

        // Front-batch all global loads (coalesced 128B per LDG instruction).
        int   c[CPT];
        float s[CPT];
        #pragma unroll
        for (int k = 0; k < CPT; k++)
            c[k] = __ldg(cp + k * 32 + lane);
        #pragma unroll
        for (int k = 0; k < CPT; k++)
            s[k] = __ldg(sp + ((k * 32 + lane) >> 4));

        // Wait until the bulk store issued 2 iterations ago (same buffer)
        // has finished reading this warp's slab. Per-warp group chain:
        // only lane 0 issues/commits, so only lane 0 waits.
        if (lane == 0)
            asm volatile("cp.async.bulk.wait_group.read 1;" ::: "memory");
        __syncwarp();

        // Gather + scale -> this warp's smem slab.
        float4* ob = &s_out[wid][buf][0];
        #pragma unroll
        for (int k = 0; k < CPT; k++) {
            float4 v = s_cb[cb_off + c[k]];
            v.x *= s[k]; v.y *= s[k]; v.z *= s[k]; v.w *= s[k];
            ob[k * 32 + lane] = v;
        }
        __syncwarp();

        // One lane streams the 4KB warp-tile to GMEM as a single burst.
        if (lane == 0) {
            asm volatile("fence.proxy.async.shared::cta;" ::: "memory");
            asm volatile(
                "cp.async.bulk.global.shared::cta.bulk_group [%0], [%1], %2;"
                :: "l"(out4 + base), "r"(smem_u32(ob)), "n"(WT_BYTES)
                : "memory");
            asm volatile("cp.async.bulk.commit_group;" ::: "memory");
        }
    }

    // Drain this warp's outstanding bulk stores before exit.
    if (lane == 0)
        asm volatile("cp.async.bulk.wait_group 0;" ::: "memory");
}

extern "C" void kernel_launch(void* const* d_in, const int* in_sizes, int n_in,
                              void* d_out, int out_size)
{
    // metadata order: codebooks [2,256,4] f32, scales [1M,1] f32, codes [2,8M] i32, rows, columns
    const float4* codebooks = (const float4*)d_in[0];
    const float*  scales    = (const float*)d_in[1];
    const int*    codes     = (const int*)d_in[2];
    float4*       out4      = (float4*)d_out;

    dequant_kernel<<<GRID, BLOCK>>>(codebooks, scales, codes, out4);
}

// round 15
// speedup vs baseline: 1.0587x; 1.0587x over previous
#include <cuda_runtime.h>
#include <cstdint>

// Problem constants (fixed by the reference).
#define ROWS       8192
#define COLS       8192
#define NUMEL      (1ULL * ROWS * COLS)          // 64M output floats
#define NCODES     (NUMEL / 4)                   // 16M codes (centroid_len = 4)
#define CB_ENTRIES 512                           // 2 codebooks * 256 centroids (float4)

#define BLOCK      256
#define CPT        8                               // codes per thread per tile
#define TILE_CODES (BLOCK * CPT)                   // 2048 codes
#define TILE_BYTES (TILE_CODES * 16)               // 32 KB output per tile
#define NTILES     ((int)(NCODES / TILE_CODES))    // 8192 (exact)
#define DEPTH      2
#define GRID       (152 * 3)                       // 456 blocks (72KB smem -> 3/SM)

// R8 structure scaled up: compute a 32KB output tile into smem (double
// buffered), one cp.async.bulk per tile streams it to GMEM as a single
// contiguous burst. Halves barrier/issue overhead per byte vs 16KB tiles
// and doubles the DRAM write burst size (the only lever that has moved perf).

__device__ __forceinline__ uint32_t smem_u32(const void* p) {
    uint32_t a;
    asm("{ .reg .u64 t; cvta.to.shared.u64 t, %1; cvt.u32.u64 %0, t; }"
        : "=r"(a) : "l"(p));
    return a;
}

__global__ __launch_bounds__(BLOCK) void dequant_kernel(
    const float4* __restrict__ codebooks,   // [512] float4
    const float*  __restrict__ scales,      // [NUMEL/64]
    const int*    __restrict__ codes,       // [NCODES]
    float4*       __restrict__ out4)        // [NCODES]
{
    __shared__ float4 s_cb[CB_ENTRIES];                    // 8 KB
    __shared__ __align__(128) float4 s_out[DEPTH][TILE_CODES]; // 2 x 32 KB

    for (int i = threadIdx.x; i < CB_ENTRIES; i += BLOCK)
        s_cb[i] = codebooks[i];
    __syncthreads();

    const int t      = threadIdx.x;
    const int stride = gridDim.x;

    int iter = 0;
    for (int tile = blockIdx.x; tile < NTILES; tile += stride, iter++) {
        const int buf = iter & 1;
        const long long base = (long long)tile * TILE_CODES;
        // First 4096 tiles lie entirely in codebook 0, rest in codebook 1.
        const int cb_off = (tile >= (NTILES / 2)) ? 256 : 0;

        const int*   cp = codes  + base;
        const float* sp = scales + (base >> 4);

        // Front-batch global loads (all in flight across the barrier below).
        int   c[CPT];
        float s[CPT];
        #pragma unroll
        for (int k = 0; k < CPT; k++)
            c[k] = __ldg(cp + k * BLOCK + t);
        #pragma unroll
        for (int k = 0; k < CPT; k++)
            s[k] = __ldg(sp + ((k * BLOCK + t) >> 4));

        // Ensure the TMA store issued 2 iterations ago (same buffer) has
        // finished READING this smem buffer before we overwrite it.
        if (iter >= DEPTH && t == 0)
            asm volatile("cp.async.bulk.wait_group.read %0;" :: "n"(DEPTH - 1) : "memory");
        __syncthreads();

        // Gather + scale -> smem tile (interleaved STS.128, conflict-free).
        #pragma unroll
        for (int k = 0; k < CPT; k++) {
            float4 v = s_cb[cb_off + c[k]];
            v.x *= s[k]; v.y *= s[k]; v.z *= s[k]; v.w *= s[k];
            s_out[buf][k * BLOCK + t] = v;
        }
        __syncthreads();

        // One thread issues the bulk async store of the whole 32KB tile.
        if (t == 0) {
            asm volatile("fence.proxy.async.shared::cta;" ::: "memory");
            asm volatile(
                "cp.async.bulk.global.shared::cta.bulk_group [%0], [%1], %2;"
                :: "l"(out4 + base), "r"(smem_u32(&s_out[buf][0])), "n"(TILE_BYTES)
                : "memory");
            asm volatile("cp.async.bulk.commit_group;" ::: "memory");
        }
    }

    // Drain all outstanding bulk stores before exit.
    if (t == 0)
        asm volatile("cp.async.bulk.wait_group 0;" ::: "memory");
}

extern "C" void kernel_launch(void* const* d_in, const int* in_sizes, int n_in,
                              void* d_out, int out_size)
{
    // metadata order: codebooks [2,256,4] f32, scales [1M,1] f32, codes [2,8M] i32, rows, columns
    const float4* codebooks = (const float4*)d_in[0];
    const float*  scales    = (const float*)d_in[1];
    const int*    codes     = (const int*)d_in[2];
    float4*       out4      = (float4*)d_out;

    int grid = GRID;
    if (grid > NTILES) grid = NTILES;

    dequant_kernel<<<grid, BLOCK>>>(codebooks, scales, codes, out4);
}